// round 14
// baseline (speedup 1.0000x reference)
#include <cuda_runtime.h>
#include <cuda_bf16.h>
#include <cstdint>

// Chamfer loss, B=4, N=M=8192, D=3.
//   dist(i,j) = ||a_i||^2 + ( ||b_j||^2 - 2 a_i . b_j )
// 2 launches:
//   pack_kernel: packs both sets into global quads {-2b0[4],-2b1[4],-2b2[4],n[4]}
//                + inits min slots + reduce ticket.
//   chamfer_kernel: 2048 blocks (dir x batch x 16 B-slices x 16 A-chunks);
//                loads its 8KB packed B-slice to smem once; thread holds 4 A pts;
//                per B-group: 4 LDS.128 + 24 FFMA2 (binder) + 16 FMNMX tournament;
//                atomicMin merge (nonneg float-as-uint, deterministic);
//                last-block folds the 64K mins in fixed order -> mean.
// R8 postmortem: per-block B-pack was 16x redundant (-> reverted to global pack);
// occupancy was the limiter (occ 40%, issue 59%) -> tournament min (-12 regs) +
// __launch_bounds__(128,10) for 62.5% occ.

#define BATCH   4
#define NPTS    8192
#define GROUPS  (NPTS / 4)       // 2048
#define SB      16               // B slices
#define SLICE_G (GROUPS / SB)    // 128 groups = 512 B points = 8KB packed
#define BLK     128
#define APT     4                // A points per thread
#define ACHUNK  (BLK * APT)      // 512
#define NCHUNK  (NPTS / ACHUNK)  // 16
#define NMINS   (2 * BATCH * NPTS)   // 65536
#define TOTBLKS (NCHUNK * BATCH * 2 * SB)  // 2048

__device__ float    g_packedX[BATCH * GROUPS * 16];
__device__ float    g_packedY[BATCH * GROUPS * 16];
__device__ unsigned g_minbits[NMINS];
__device__ unsigned g_ticket;

#define FMA_F32X2(d, a, b, c) \
    asm("fma.rn.f32x2 %0, %1, %2, %3;" : "=l"(d) : "l"(a), "l"(b), "l"(c))
#define PACK2_SAME(out, r) \
    asm("mov.b64 %0, {%1, %1};" : "=l"(out) : "r"(r))
#define UNPACK_F32X2(lo, hi, in) \
    asm("mov.b64 {%0, %1}, %2;" : "=r"(lo), "=r"(hi) : "l"(in))

// blocks [0,128): pack x + init minbits[0,32768)
// blocks [128,256): pack y + init minbits[32768,65536)
__global__ __launch_bounds__(256) void pack_kernel(
    const float* __restrict__ x, const float* __restrict__ y)
{
    if (blockIdx.x == 0 && threadIdx.x == 0) g_ticket = 0;

    int which = (blockIdx.x >= 128);
    int idx = (blockIdx.x & 127) * 256 + threadIdx.x;   // 0 .. BATCH*NPTS-1

    g_minbits[which * (BATCH * NPTS) + idx] = 0x7F800000u;

    const float* __restrict__ src = which ? y : x;
    float* __restrict__ dst = which ? g_packedY : g_packedX;

    int b = idx >> 13;
    int j = idx & (NPTS - 1);
    float s0 = src[(size_t)idx * 3 + 0];
    float s1 = src[(size_t)idx * 3 + 1];
    float s2 = src[(size_t)idx * 3 + 2];
    int g = j >> 2, l = j & 3;
    float* base = dst + ((size_t)(b * GROUPS + g)) * 16;
    base[0  + l] = -2.0f * s0;
    base[4  + l] = -2.0f * s1;
    base[8  + l] = -2.0f * s2;
    base[12 + l] = s0 * s0 + s1 * s1 + s2 * s2;
}

__global__ __launch_bounds__(BLK, 10) void chamfer_kernel(
    const float* __restrict__ x, const float* __restrict__ y,
    float* __restrict__ out)
{
    __shared__ float4 sy[SLICE_G * 4];               // 8 KB packed B slice
    __shared__ float  sred[BLK];
    __shared__ bool   islast;

    int dir   = blockIdx.z >> 4;                     // 0: x->y, 1: y->x
    int slice = blockIdx.z & (SB - 1);
    int b     = blockIdx.y;
    int chunk = blockIdx.x;

    const float* __restrict__ A       = dir ? y : x;
    const float* __restrict__ packedB = dir ? g_packedX : g_packedY;

    // Load this block's packed B-slice into smem (512 float4 / 128 thr = 4 each)
    const float4* gsrc = (const float4*)(packedB +
        ((size_t)(b * GROUPS + slice * SLICE_G)) * 16);
    #pragma unroll
    for (int k = 0; k < SLICE_G * 4 / BLK; ++k)
        sy[threadIdx.x + k * BLK] = gsrc[threadIdx.x + k * BLK];

    // Load 4 consecutive A points (48B, 16B-aligned) as 3 float4
    int i0 = chunk * ACHUNK + threadIdx.x * APT;
    const float4* ap = (const float4*)(A + ((size_t)b * NPTS + i0) * 3);
    float4 q0 = ap[0], q1 = ap[1], q2 = ap[2];

    float a0c[APT] = {q0.x, q0.w, q1.z, q2.y};
    float a1c[APT] = {q0.y, q1.x, q1.w, q2.z};
    float a2c[APT] = {q0.z, q1.y, q2.x, q2.w};

    unsigned long long ax[APT], ay[APT], az[APT];
    float a2n[APT];
    #pragma unroll
    for (int j = 0; j < APT; ++j) {
        PACK2_SAME(ax[j], __float_as_uint(a0c[j]));
        PACK2_SAME(ay[j], __float_as_uint(a1c[j]));
        PACK2_SAME(az[j], __float_as_uint(a2c[j]));
        a2n[j] = a0c[j]*a0c[j] + a1c[j]*a1c[j] + a2c[j]*a2c[j];
    }

    float m[APT];
    #pragma unroll
    for (int j = 0; j < APT; ++j) m[j] = 1e30f;

    __syncthreads();

    // Main loop: 128 groups x (4 LDS.128 + 24 FFMA2 + 16 FMNMX tournament)
    const ulonglong2* sp = (const ulonglong2*)sy;
    #pragma unroll 2
    for (int g = 0; g < SLICE_G; ++g) {
        ulonglong2 p0 = sp[g * 4 + 0];   // {-2b0 ab, -2b0 cd}
        ulonglong2 p1 = sp[g * 4 + 1];   // {-2b1 ab, -2b1 cd}
        ulonglong2 p2 = sp[g * 4 + 2];   // {-2b2 ab, -2b2 cd}
        ulonglong2 p3 = sp[g * 4 + 3];   // {n   ab,  n   cd}

        #pragma unroll
        for (int j = 0; j < APT; ++j) {
            unsigned long long tab, tcd;
            FMA_F32X2(tab, ax[j], p0.x, p3.x);
            FMA_F32X2(tcd, ax[j], p0.y, p3.y);
            FMA_F32X2(tab, ay[j], p1.x, tab);
            FMA_F32X2(tcd, ay[j], p1.y, tcd);
            FMA_F32X2(tab, az[j], p2.x, tab);
            FMA_F32X2(tcd, az[j], p2.y, tcd);

            unsigned lo1, hi1, lo2, hi2;
            UNPACK_F32X2(lo1, hi1, tab);
            UNPACK_F32X2(lo2, hi2, tcd);
            float t1 = fminf(__uint_as_float(lo1), __uint_as_float(hi1));
            float t2 = fminf(__uint_as_float(lo2), __uint_as_float(hi2));
            m[j] = fminf(m[j], fminf(t1, t2));
        }
    }

    // Add ||a||^2, clamp >=0 (uint-min ordering exact), merge slices
    unsigned base = (unsigned)((dir * BATCH + b) * NPTS + i0);
    #pragma unroll
    for (int j = 0; j < APT; ++j) {
        float val = fmaxf(a2n[j] + m[j], 0.0f);
        atomicMin(&g_minbits[base + j], __float_as_uint(val));
    }

    // Last-block final reduction (threadFenceReduction pattern)
    __threadfence();
    __syncthreads();
    if (threadIdx.x == 0) {
        unsigned t = atomicAdd(&g_ticket, 1u);
        islast = (t == TOTBLKS - 1);
    }
    __syncthreads();

    if (islast) {
        __threadfence();                 // acquire: see all blocks' mins
        const uint4* src = (const uint4*)g_minbits;
        float sum = 0.0f;
        for (int k = 0; k < NMINS / 4 / BLK; ++k) {   // fixed per-thread order
            uint4 v = src[threadIdx.x + k * BLK];
            sum += __uint_as_float(v.x) + __uint_as_float(v.y)
                 + __uint_as_float(v.z) + __uint_as_float(v.w);
        }
        sred[threadIdx.x] = sum;
        __syncthreads();
        #pragma unroll
        for (int st = BLK / 2; st > 0; st >>= 1) {
            if (threadIdx.x < st) sred[threadIdx.x] += sred[threadIdx.x + st];
            __syncthreads();
        }
        if (threadIdx.x == 0)
            out[0] = sred[0] * (1.0f / (float)(BATCH * NPTS));
    }
}

extern "C" void kernel_launch(void* const* d_in, const int* in_sizes, int n_in,
                              void* d_out, int out_size)
{
    (void)in_sizes; (void)n_in; (void)out_size;
    const float* x = (const float*)d_in[0];
    const float* y = (const float*)d_in[1];
    float* out = (float*)d_out;

    pack_kernel<<<256, 256>>>(x, y);    // pack both sets + init mins + ticket

    dim3 grid(NCHUNK, BATCH, 2 * SB);   // 16 x 4 x 32 = 2048 blocks
    chamfer_kernel<<<grid, BLK>>>(x, y, out);
}

// round 17
// speedup vs baseline: 1.0628x; 1.0628x over previous
#include <cuda_runtime.h>
#include <cuda_bf16.h>
#include <cstdint>

// Chamfer loss, B=4, N=M=8192, D=3.
//   dist(i,j) = ||a_i||^2 + ( ||b_j||^2 - 2 a_i . b_j )
// 2 launches: pack(+init+ticket), chamfer(+last-block reduce).
// R14 postmortem: occupancy theory dead (occ 40->45%, issue 59->55%, dur flat).
// Measured 79 cyc/group vs 42 instrs => FFMA2 issuing at rt~3 (RF banking:
// 3 distinct 64-bit operand pairs = 3 even + 3 odd distinct regs).
// Fix: wave-reordered inner loop -- 4 consecutive FFMA2 share the b (and c)
// operand slot => reuse drops distinct banks to 1-2 => rt=2 => 48 cyc/group.

#define BATCH   4
#define NPTS    8192
#define GROUPS  (NPTS / 4)       // 2048
#define SB      16               // B slices
#define SLICE_G (GROUPS / SB)    // 128 groups = 512 B points = 8KB packed
#define BLK     128
#define APT     4                // A points per thread
#define ACHUNK  (BLK * APT)      // 512
#define NCHUNK  (NPTS / ACHUNK)  // 16
#define NMINS   (2 * BATCH * NPTS)   // 65536
#define TOTBLKS (NCHUNK * BATCH * 2 * SB)  // 2048

__device__ float    g_packedX[BATCH * GROUPS * 16];
__device__ float    g_packedY[BATCH * GROUPS * 16];
__device__ unsigned g_minbits[NMINS];
__device__ unsigned g_ticket;

#define FMA_F32X2(d, a, b, c) \
    asm("fma.rn.f32x2 %0, %1, %2, %3;" : "=l"(d) : "l"(a), "l"(b), "l"(c))
#define PACK2_SAME(out, r) \
    asm("mov.b64 %0, {%1, %1};" : "=l"(out) : "r"(r))
#define UNPACK_F32X2(lo, hi, in) \
    asm("mov.b64 {%0, %1}, %2;" : "=r"(lo), "=r"(hi) : "l"(in))

// blocks [0,128): pack x + init minbits[0,32768)
// blocks [128,256): pack y + init minbits[32768,65536)
__global__ __launch_bounds__(256) void pack_kernel(
    const float* __restrict__ x, const float* __restrict__ y)
{
    if (blockIdx.x == 0 && threadIdx.x == 0) g_ticket = 0;

    int which = (blockIdx.x >= 128);
    int idx = (blockIdx.x & 127) * 256 + threadIdx.x;   // 0 .. BATCH*NPTS-1

    g_minbits[which * (BATCH * NPTS) + idx] = 0x7F800000u;

    const float* __restrict__ src = which ? y : x;
    float* __restrict__ dst = which ? g_packedY : g_packedX;

    int b = idx >> 13;
    int j = idx & (NPTS - 1);
    float s0 = src[(size_t)idx * 3 + 0];
    float s1 = src[(size_t)idx * 3 + 1];
    float s2 = src[(size_t)idx * 3 + 2];
    int g = j >> 2, l = j & 3;
    float* base = dst + ((size_t)(b * GROUPS + g)) * 16;
    base[0  + l] = -2.0f * s0;
    base[4  + l] = -2.0f * s1;
    base[8  + l] = -2.0f * s2;
    base[12 + l] = s0 * s0 + s1 * s1 + s2 * s2;
}

__global__ __launch_bounds__(BLK, 8) void chamfer_kernel(
    const float* __restrict__ x, const float* __restrict__ y,
    float* __restrict__ out)
{
    __shared__ float4 sy[SLICE_G * 4];               // 8 KB packed B slice
    __shared__ float  sred[BLK];
    __shared__ bool   islast;

    int dir   = blockIdx.z >> 4;                     // 0: x->y, 1: y->x
    int slice = blockIdx.z & (SB - 1);
    int b     = blockIdx.y;
    int chunk = blockIdx.x;

    const float* __restrict__ A       = dir ? y : x;
    const float* __restrict__ packedB = dir ? g_packedX : g_packedY;

    // Load this block's packed B-slice into smem (512 float4 / 128 thr = 4 each)
    const float4* gsrc = (const float4*)(packedB +
        ((size_t)(b * GROUPS + slice * SLICE_G)) * 16);
    #pragma unroll
    for (int k = 0; k < SLICE_G * 4 / BLK; ++k)
        sy[threadIdx.x + k * BLK] = gsrc[threadIdx.x + k * BLK];

    // Load 4 consecutive A points (48B, 16B-aligned) as 3 float4
    int i0 = chunk * ACHUNK + threadIdx.x * APT;
    const float4* ap = (const float4*)(A + ((size_t)b * NPTS + i0) * 3);
    float4 q0 = ap[0], q1 = ap[1], q2 = ap[2];

    float a0c[APT] = {q0.x, q0.w, q1.z, q2.y};
    float a1c[APT] = {q0.y, q1.x, q1.w, q2.z};
    float a2c[APT] = {q0.z, q1.y, q2.x, q2.w};

    unsigned long long ax[APT], ay[APT], az[APT];
    float a2n[APT];
    #pragma unroll
    for (int j = 0; j < APT; ++j) {
        PACK2_SAME(ax[j], __float_as_uint(a0c[j]));
        PACK2_SAME(ay[j], __float_as_uint(a1c[j]));
        PACK2_SAME(az[j], __float_as_uint(a2c[j]));
        a2n[j] = a0c[j]*a0c[j] + a1c[j]*a1c[j] + a2c[j]*a2c[j];
    }

    float m[APT];
    #pragma unroll
    for (int j = 0; j < APT; ++j) m[j] = 1e30f;

    __syncthreads();

    // Main loop, wave-ordered for operand-slot reuse:
    //   wave: 4 FFMA2 with identical b (and c) operands -> RF bank reuse -> rt=2
    const ulonglong2* sp = (const ulonglong2*)sy;
    unsigned long long t[APT];
    #pragma unroll 1
    for (int g = 0; g < SLICE_G; ++g) {
        ulonglong2 p0 = sp[g * 4 + 0];   // {-2b0 ab, -2b0 cd}
        ulonglong2 p1 = sp[g * 4 + 1];   // {-2b1 ab, -2b1 cd}
        ulonglong2 p2 = sp[g * 4 + 2];   // {-2b2 ab, -2b2 cd}
        ulonglong2 p3 = sp[g * 4 + 3];   // {n   ab,  n   cd}

        // ---- ab halves (points 0,1 of the quad) ----
        #pragma unroll
        for (int j = 0; j < APT; ++j) FMA_F32X2(t[j], ax[j], p0.x, p3.x);
        #pragma unroll
        for (int j = 0; j < APT; ++j) FMA_F32X2(t[j], ay[j], p1.x, t[j]);
        #pragma unroll
        for (int j = 0; j < APT; ++j) FMA_F32X2(t[j], az[j], p2.x, t[j]);
        #pragma unroll
        for (int j = 0; j < APT; ++j) {
            unsigned lo, hi;
            UNPACK_F32X2(lo, hi, t[j]);
            m[j] = fminf(m[j], fminf(__uint_as_float(lo), __uint_as_float(hi)));
        }

        // ---- cd halves (points 2,3 of the quad) ----
        #pragma unroll
        for (int j = 0; j < APT; ++j) FMA_F32X2(t[j], ax[j], p0.y, p3.y);
        #pragma unroll
        for (int j = 0; j < APT; ++j) FMA_F32X2(t[j], ay[j], p1.y, t[j]);
        #pragma unroll
        for (int j = 0; j < APT; ++j) FMA_F32X2(t[j], az[j], p2.y, t[j]);
        #pragma unroll
        for (int j = 0; j < APT; ++j) {
            unsigned lo, hi;
            UNPACK_F32X2(lo, hi, t[j]);
            m[j] = fminf(m[j], fminf(__uint_as_float(lo), __uint_as_float(hi)));
        }
    }

    // Add ||a||^2, clamp >=0 (uint-min ordering exact), merge slices
    unsigned base = (unsigned)((dir * BATCH + b) * NPTS + i0);
    #pragma unroll
    for (int j = 0; j < APT; ++j) {
        float val = fmaxf(a2n[j] + m[j], 0.0f);
        atomicMin(&g_minbits[base + j], __float_as_uint(val));
    }

    // Last-block final reduction (threadFenceReduction pattern)
    __threadfence();
    __syncthreads();
    if (threadIdx.x == 0) {
        unsigned t2 = atomicAdd(&g_ticket, 1u);
        islast = (t2 == TOTBLKS - 1);
    }
    __syncthreads();

    if (islast) {
        __threadfence();                 // acquire: see all blocks' mins
        const uint4* src = (const uint4*)g_minbits;
        float sum = 0.0f;
        for (int k = 0; k < NMINS / 4 / BLK; ++k) {   // fixed per-thread order
            uint4 v = src[threadIdx.x + k * BLK];
            sum += __uint_as_float(v.x) + __uint_as_float(v.y)
                 + __uint_as_float(v.z) + __uint_as_float(v.w);
        }
        sred[threadIdx.x] = sum;
        __syncthreads();
        #pragma unroll
        for (int st = BLK / 2; st > 0; st >>= 1) {
            if (threadIdx.x < st) sred[threadIdx.x] += sred[threadIdx.x + st];
            __syncthreads();
        }
        if (threadIdx.x == 0)
            out[0] = sred[0] * (1.0f / (float)(BATCH * NPTS));
    }
}

extern "C" void kernel_launch(void* const* d_in, const int* in_sizes, int n_in,
                              void* d_out, int out_size)
{
    (void)in_sizes; (void)n_in; (void)out_size;
    const float* x = (const float*)d_in[0];
    const float* y = (const float*)d_in[1];
    float* out = (float*)d_out;

    pack_kernel<<<256, 256>>>(x, y);    // pack both sets + init mins + ticket

    dim3 grid(NCHUNK, BATCH, 2 * SB);   // 16 x 4 x 32 = 2048 blocks
    chamfer_kernel<<<grid, BLK>>>(x, y, out);
}